// round 12
// baseline (speedup 1.0000x reference)
#include <cuda_runtime.h>
#include <cstdint>
#include <cstddef>

constexpr int B=256, T=64, H=512, S=32, C=32, A_=32, E=1024, BS=256;
constexpr int D=2048, X3H=1536, INX=1056, G3=768, NG=6144, DE_IN=3072, SC=1024;
constexpr int NBLK=296, NTH=256;
typedef unsigned long long u64;

__device__ __align__(16) float g_deter[B*D];
__device__ __align__(16) float g_xin [B*INX];
__device__ __align__(16) float g_xp  [2*B*X3H];   // x partials (split2, raw)
__device__ __align__(16) float g_hp  [4*B*D];     // h partials NEXT step (split4, masked)
__device__ __align__(16) float g_gip [3*B*NG];    // gi partials (split3, raw)
__device__ __align__(16) float g_gh  [B*NG];      // gh (biased)
__device__ __align__(16) float g_dein[B*DE_IN];
__device__ __align__(16) float g_dp  [6*B*D];     // de partials (split6, raw)
__device__ __align__(16) float g_h1  [4*2*B*H];   // M=512 (prior|post), split4 raw
__device__ __align__(16) float g_h2  [4*2*B*H];   // split4 raw
__device__ __align__(16) float g_lp  [4*2*B*SC];  // logits partials (split4 raw)
__device__ unsigned g_cnt;
__device__ unsigned g_gen;
__device__ unsigned g_ctr[6*T];

// ----------------------------- packed f32x2 --------------------------------
__device__ __forceinline__ u64 pk2(float x) {
  u64 r; asm("mov.b64 %0,{%1,%1};" : "=l"(r) : "f"(x)); return r;
}
__device__ __forceinline__ void fma2(u64& d, u64 a, u64 b) {
  asm("fma.rn.f32x2 %0,%1,%2,%0;" : "+l"(d) : "l"(a), "l"(b));
}
__device__ __forceinline__ float2 up2(u64 v) {
  float2 r; asm("mov.b64 {%0,%1},%2;" : "=f"(r.x), "=f"(r.y) : "l"(v)); return r;
}

// ----------------------------- grid barrier --------------------------------
__device__ __forceinline__ void gridbar() {
  __syncthreads();
  if (threadIdx.x == 0) {
    unsigned gen = *(volatile unsigned*)&g_gen;
    __threadfence();
    if (atomicAdd(&g_cnt, 1u) == gridDim.x - 1u) {
      g_cnt = 0u;
      __threadfence();
      atomicExch(&g_gen, gen + 1u);
    } else {
      while (*(volatile unsigned*)&g_gen == gen) {}
    }
    __threadfence();
  }
  __syncthreads();
}

// ------------------------------ threefry2x32 -------------------------------
__device__ __forceinline__ void threefry(uint32_t k0, uint32_t k1, uint32_t x0,
                                         uint32_t x1, uint32_t& o0, uint32_t& o1) {
  uint32_t ks2 = 0x1BD11BDAu ^ k0 ^ k1;
#define TFR(x,r) x = (x<<r)|(x>>(32-r))
#define TF4(a,b,c,d) x0+=x1;TFR(x1,a);x1^=x0; x0+=x1;TFR(x1,b);x1^=x0; x0+=x1;TFR(x1,c);x1^=x0; x0+=x1;TFR(x1,d);x1^=x0;
  x0 += k0; x1 += k1;
  TF4(13,15,26,6);  x0 += k1;  x1 += ks2 + 1u;
  TF4(17,29,16,24); x0 += ks2; x1 += k0 + 2u;
  TF4(13,15,26,6);  x0 += k0;  x1 += k1 + 3u;
  TF4(17,29,16,24); x0 += k1;  x1 += ks2 + 4u;
  TF4(13,15,26,6);  x0 += ks2; x1 += k0 + 5u;
  o0 = x0; o1 = x1;
#undef TF4
#undef TFR
}

__device__ __forceinline__ float silu1(float v) { return v/(1.0f+expf(-v)); }

// ------------------------------ GEMM tile 128x64 ---------------------------
// C[m0..m0+128, n0..n0+64) (+)= Aeff[:,kbase..+IN2) @ W[n,kbase..+IN2)^T
// Aeff: NP=1 plain A0; NP>=2: (sum of NP partials)+Abias, optional SiLU.
// 256 threads, per-thread 8 rows x 4 cols, FFMA2 paired along rows.
// As: float [16][136] (rows adjacent -> natural u64 row pairs).
// Ws2: u64 [16][68], each entry {w,w} duplicated (packed at fill).
template <int NP,int SILU,int WMODE,int MASKED>
__device__ __forceinline__ void gemm(
    const float* __restrict__ A0, size_t pstr,
    const float* __restrict__ Abias, int lda,
    const float* __restrict__ W, int ldw, const float* __restrict__ bias,
    float* __restrict__ Cb, int ldc,
    int IN2, int kbase, int m0, int n0, int aColBase,
    const int* __restrict__ isf, int mt,
    float (*As)[136], u64 (*Ws2)[68], float* mrow) {
  const int tid = threadIdx.x;
  if (MASKED) { if (tid < 128) mrow[tid] = isf[(size_t)(m0+tid)*T + mt] ? 0.0f : 1.0f; }
  __syncthreads();
  const int aoff = aColBase + kbase;
  const float* Ab0 = A0 + (size_t)m0*lda + aoff;
  const float* Wb  = W + (size_t)n0*ldw + kbase;
  const int alr = tid>>1, alq = (tid&1)<<3;    // a: row 0..127, kcol 0/8
  const int wlr = tid>>2, wlq = (tid&3)<<2;    // w: row 0..63,  kcol 0..12
  const int ty = tid>>4, tx = tid&15;          // out: 8 rows (4 pairs), 4 cols
  u64 acc[4][4] = {};                          // [rowpair][col]
  for (int k0 = 0; k0 < IN2; k0 += 16) {
    size_t ao = (size_t)alr*lda + k0 + alq;
    float4 av0 = *(const float4*)(Ab0 + ao);
    float4 av1 = *(const float4*)(Ab0 + ao + 4);
    if (NP>=2) {
#pragma unroll
      for (int p = 1; p < NP; p++) {
        float4 b0v = *(const float4*)(Ab0 + p*pstr + ao);
        float4 b1v = *(const float4*)(Ab0 + p*pstr + ao + 4);
        av0.x += b0v.x; av0.y += b0v.y; av0.z += b0v.z; av0.w += b0v.w;
        av1.x += b1v.x; av1.y += b1v.y; av1.z += b1v.z; av1.w += b1v.w;
      }
      float4 ab0 = *(const float4*)(Abias + aoff + k0 + alq);
      float4 ab1 = *(const float4*)(Abias + aoff + k0 + alq + 4);
      av0.x += ab0.x; av0.y += ab0.y; av0.z += ab0.z; av0.w += ab0.w;
      av1.x += ab1.x; av1.y += ab1.y; av1.z += ab1.z; av1.w += ab1.w;
      if (SILU) {
        av0.x=silu1(av0.x); av0.y=silu1(av0.y); av0.z=silu1(av0.z); av0.w=silu1(av0.w);
        av1.x=silu1(av1.x); av1.y=silu1(av1.y); av1.z=silu1(av1.z); av1.w=silu1(av1.w);
      }
    }
    if (MASKED) {
      float mm = mrow[alr];
      av0.x*=mm; av0.y*=mm; av0.z*=mm; av0.w*=mm;
      av1.x*=mm; av1.y*=mm; av1.z*=mm; av1.w*=mm;
    }
    As[alq+0][alr]=av0.x; As[alq+1][alr]=av0.y; As[alq+2][alr]=av0.z; As[alq+3][alr]=av0.w;
    As[alq+4][alr]=av1.x; As[alq+5][alr]=av1.y; As[alq+6][alr]=av1.z; As[alq+7][alr]=av1.w;
    float4 wv = *(const float4*)(Wb + (size_t)wlr*ldw + k0 + wlq);
    Ws2[wlq+0][wlr]=pk2(wv.x); Ws2[wlq+1][wlr]=pk2(wv.y);
    Ws2[wlq+2][wlr]=pk2(wv.z); Ws2[wlq+3][wlr]=pk2(wv.w);
    __syncthreads();
#pragma unroll
    for (int kk = 0; kk < 16; kk++) {
      ulonglong2 a01 = *(const ulonglong2*)&As[kk][ty<<3];       // row pairs 0,1
      ulonglong2 a23 = *(const ulonglong2*)&As[kk][(ty<<3)+4];   // row pairs 2,3
      ulonglong2 w01 = *(const ulonglong2*)&Ws2[kk][tx<<2];      // cols 0,1 (dup)
      ulonglong2 w23 = *(const ulonglong2*)&Ws2[kk][(tx<<2)+2];  // cols 2,3 (dup)
      u64 ar0=a01.x, ar1=a01.y, ar2=a23.x, ar3=a23.y;
      u64 wc0=w01.x, wc1=w01.y, wc2=w23.x, wc3=w23.y;
      fma2(acc[0][0],ar0,wc0); fma2(acc[0][1],ar0,wc1);
      fma2(acc[0][2],ar0,wc2); fma2(acc[0][3],ar0,wc3);
      fma2(acc[1][0],ar1,wc0); fma2(acc[1][1],ar1,wc1);
      fma2(acc[1][2],ar1,wc2); fma2(acc[1][3],ar1,wc3);
      fma2(acc[2][0],ar2,wc0); fma2(acc[2][1],ar2,wc1);
      fma2(acc[2][2],ar2,wc2); fma2(acc[2][3],ar2,wc3);
      fma2(acc[3][0],ar3,wc0); fma2(acc[3][1],ar3,wc1);
      fma2(acc[3][2],ar3,wc2); fma2(acc[3][3],ar3,wc3);
    }
    __syncthreads();
  }
#pragma unroll
  for (int r2 = 0; r2 < 4; r2++) {
    int mi = m0 + (ty<<3) + (r2<<1);       // rows mi, mi+1
    int nb = n0 + (tx<<2);
    float2 c0 = up2(acc[r2][0]), c1 = up2(acc[r2][1]);
    float2 c2 = up2(acc[r2][2]), c3 = up2(acc[r2][3]);
    float4 va, vb;
    va.x=c0.x; va.y=c1.x; va.z=c2.x; va.w=c3.x;
    vb.x=c0.y; vb.y=c1.y; vb.z=c2.y; vb.w=c3.y;
    if (WMODE==0) {
      float4 bv = *(const float4*)(bias + nb);
      va.x+=bv.x; va.y+=bv.y; va.z+=bv.z; va.w+=bv.w;
      vb.x+=bv.x; vb.y+=bv.y; vb.z+=bv.z; vb.w+=bv.w;
    }
    *(float4*)(Cb + (size_t)mi*ldc + nb) = va;
    *(float4*)(Cb + (size_t)(mi+1)*ldc + nb) = vb;
  }
}

// ------------------------------ megakernel ---------------------------------
__global__ void __launch_bounds__(NTH, 2) k_rssm(
    const float* __restrict__ embed, const float* __restrict__ actions,
    const int* __restrict__ isf,
    const float* __restrict__ W_in,  const float* __restrict__ b_in,
    const float* __restrict__ W_blk, const float* __restrict__ b_blk,
    const float* __restrict__ W_ih,  const float* __restrict__ b_ih,
    const float* __restrict__ W_hh,  const float* __restrict__ b_hh,
    const float* __restrict__ W1,    const float* __restrict__ b1,
    const float* __restrict__ W2,    const float* __restrict__ b2,
    const float* __restrict__ W3,    const float* __restrict__ b3,
    const float* __restrict__ W_proj,const float* __restrict__ b_proj,
    float* __restrict__ out_deter, float* __restrict__ out_stoch,
    float* __restrict__ out_prior, float* __restrict__ out_post) {
  __shared__ __align__(16) float As[16][136];
  __shared__ __align__(16) u64   Ws2[16][68];
  __shared__ float mrow[128];
  __shared__ int s_tl;
  const int bid = blockIdx.x;
  const int tid = threadIdx.x;
  const int gtid = bid*NTH + tid;
  const int gstep = gridDim.x*NTH;
  const int nwarp = gridDim.x*(NTH/32);
  const int wid = bid*(NTH/32) + (tid>>5);
  const int lane = tid & 31;
  const float TINYF = 1.17549435e-38f;
  const float UNIADD = (float)(0.01/32.0);
  const size_t PBD = (size_t)B*D;
  const size_t PBX = (size_t)B*X3H;
  const size_t PBG = (size_t)B*NG;
  const size_t PBH = (size_t)2*B*H;
  const size_t PBL = (size_t)2*B*SC;

#define POP(pid) ({ if (tid==0) s_tl = (int)atomicAdd(&g_ctr[pid], 1u); \
                    __syncthreads(); int _v = s_tl; _v; })

  for (int i = gtid; i < 6*T; i += gstep) g_ctr[i] = 0u;
  for (int i = gtid; i < B*D; i += gstep) g_deter[i] = 0.0f;
  for (size_t i = gtid; i < 4*PBD; i += gstep) g_hp[i] = 0.0f;   // h for t=0 (deter0=0)
  for (int i = gtid; i < B*INX; i += gstep) {
    int b = i/INX, j = i - b*INX;
    g_xin[i] = (j < SC) ? 0.0f : actions[((size_t)b*T)*A_ + (j-SC)];
  }
  gridbar();

  for (int t = 0; t < T; t++) {
    const int hlive = (t + 1 < T) ? 1 : 0;
    // P1: x partials (xin@W_in, split2: 96 tiles x 33ch)
    //     gh = (sum4 hp + b_blk)@W_hh + b_hh  (192 tiles x 16ch, blockdiag)
    for (;;) {
      int tl = POP(t*6+0); if (tl >= 288) break;
      if (tl < 96) {
        int p = tl/48, i = tl%48;
        gemm<1,0,1,0>(g_xin, 0, 0, INX, W_in, INX, 0,
                      g_xp + p*PBX, X3H, INX/2, p*(INX/2),
                      (i/24)<<7, (i%24)<<6, 0, 0, 0, As, Ws2, mrow);
      } else {
        int j = tl-96;
        int n0 = (j%96)<<6;
        gemm<4,0,0,0>(g_hp, PBD, b_blk, D, W_hh, BS, b_hh,
                      g_gh, NG, BS, 0,
                      (j/96)<<7, n0, (n0/G3)*BS, 0, 0, As, Ws2, mrow);
      }
    }
    gridbar();
    // P2: gi partials = silu(x-combine2 + b_in)@W_ih  (split3: 576 tiles x 32ch)
    for (;;) {
      int tl = POP(t*6+1); if (tl >= 576) break;
      int p = tl/192, i = tl%192;
      gemm<2,1,1,0>(g_xp, PBX, b_in, X3H, W_ih, X3H, 0,
                    g_gip + p*PBG, NG, X3H/3, p*(X3H/3),
                    (i/96)<<7, (i%96)<<6, 0, 0, 0, As, Ws2, mrow);
    }
    gridbar();
    // P3: GRU combine -> deter/out_deter/dein ; embed -> dein
    for (int i = gtid; i < B*D; i += gstep) {
      int b = i>>11, d = i & (D-1), k = d>>8, g = d & (BS-1);
      size_t base = (size_t)b*NG + k*G3 + g;
      float ir = (g_gip[base]      + g_gip[PBG+base])      + g_gip[2*PBG+base]      + b_ih[k*G3+g];
      float iz = (g_gip[base+BS]   + g_gip[PBG+base+BS])   + g_gip[2*PBG+base+BS]   + b_ih[k*G3+g+BS];
      float inn= (g_gip[base+2*BS] + g_gip[PBG+base+2*BS]) + g_gip[2*PBG+base+2*BS] + b_ih[k*G3+g+2*BS];
      float hr=g_gh[base], hz=g_gh[base+BS], hnn=g_gh[base+2*BS];
      float hv = ((g_hp[i] + g_hp[PBD+i]) + (g_hp[2*PBD+i] + g_hp[3*PBD+i])) + b_blk[d];
      float r = 1.0f/(1.0f+expf(-(ir+hr)));
      float z = 1.0f/(1.0f+expf(-(iz+hz)));
      float n = tanhf(inn + r*hnn);
      float dv = (1.0f - z)*n + z*hv;
      g_deter[i] = dv;
      g_dein[(size_t)b*DE_IN + d] = dv;
      out_deter[((size_t)b*T+t)*D + d] = dv;
    }
    for (int i = gtid; i < B*E; i += gstep) {
      int b = i>>10, j = i & (E-1);
      g_dein[(size_t)b*DE_IN + D + j] = embed[((size_t)b*T+t)*E + j];
    }
    gridbar();
    // P4: de partials (dein@W_proj, split6: 384 tiles x 32ch)
    //     h01 partials next step (masked deter@W_blk, split4 p=0,1: 128 x 32ch)
    {
      int nP4 = 384 + hlive*128;
      for (;;) {
        int tl = POP(t*6+2); if (tl >= nP4) break;
        if (tl < 384) {
          int p = tl/64, i = tl%64;
          gemm<1,0,1,0>(g_dein, 0, 0, DE_IN, W_proj, DE_IN, 0,
                        g_dp + p*PBD, D, DE_IN/6, p*(DE_IN/6),
                        (i/32)<<7, (i%32)<<6, 0, 0, 0, As, Ws2, mrow);
        } else {
          int j = tl-384, p = j/64, i = j%64;
          gemm<1,0,1,1>(g_deter, 0, 0, D, W_blk, D, 0,
                        g_hp + p*PBD, D, D/4, p*(D/4),
                        (i/32)<<7, (i%32)<<6, 0, isf, t+1, As, Ws2, mrow);
        }
      }
    }
    gridbar();
    // P5: h1 partials, M=512 ([deter | de-combine6+b_proj])@W1, split4: 128 x 32ch
    //     h23 partials next step (p=2,3: 128 x 32ch)
    {
      int nP5 = 128 + hlive*128;
      for (;;) {
        int tl = POP(t*6+3); if (tl >= nP5) break;
        if (tl < 128) {
          int p = tl/32, i = tl%32;
          int m0 = (i/8)<<7, n0 = (i%8)<<6;
          float* Cp = g_h1 + p*PBH;
          if (m0 < 256)
            gemm<1,0,1,0>(g_deter, 0, 0, D, W1, D, 0, Cp, H,
                          D/4, p*(D/4), m0, n0, 0, 0, 0, As, Ws2, mrow);
          else
            gemm<6,0,1,0>(g_dp - (size_t)256*D, PBD, b_proj, D, W1, D, 0,
                          Cp, H, D/4, p*(D/4), m0, n0, 0, 0, 0, As, Ws2, mrow);
        } else {
          int j = tl-128, p = 2 + j/64, i = j%64;
          gemm<1,0,1,1>(g_deter, 0, 0, D, W_blk, D, 0,
                        g_hp + p*PBD, D, D/4, p*(D/4),
                        (i/32)<<7, (i%32)<<6, 0, isf, t+1, As, Ws2, mrow);
        }
      }
    }
    gridbar();
    // P6: h2 partials = silu(h1-combine4 + b1)@W2, M=512, split4: 128 x 8ch
    for (;;) {
      int tl = POP(t*6+4); if (tl >= 128) break;
      int p = tl/32, i = tl%32;
      gemm<4,1,1,0>(g_h1, PBH, b1, H, W2, H, 0,
                    g_h2 + p*PBH, H, H/4, p*(H/4),
                    (i/8)<<7, (i%8)<<6, 0, 0, 0, As, Ws2, mrow);
    }
    gridbar();
    // P7: logit partials = silu(h2-combine4 + b2)@W3, M=512, split4: 256 x 8ch
    for (;;) {
      int tl = POP(t*6+5); if (tl >= 256) break;
      int p = tl/64, i = tl%64;
      gemm<4,1,1,0>(g_h2, PBH, b2, H, W3, H, 0,
                    g_lp + p*PBL, SC, H/4, p*(H/4),
                    (i/16)<<7, (i%16)<<6, 0, 0, 0, As, Ws2, mrow);
    }
    gridbar();
    // P8: prior combine -> out_prior ; sample(post combine) -> out_post/stoch/xin
    for (int i = gtid; i < B*SC; i += gstep) {
      int b = i>>10, j = i & (SC-1);
      out_prior[((size_t)b*T+t)*SC + j] =
        ((g_lp[i] + g_lp[PBL+i]) + (g_lp[2*PBL+i] + g_lp[3*PBL+i])) + b3[j];
    }
    {
      uint32_t k0, k1;
      threefry(0u, 42u, 0u, (uint32_t)t, k0, k1);   // fold_in(key(42), t)
      for (int gw = wid; gw < 128*32; gw += nwarp) {
        int b0 = gw >> 5, s = gw & 31;
        uint32_t nA = (uint32_t)(b0*SC + s*C + lane);
        uint32_t a0,a1,c0,c1;
        threefry(k0,k1,0u,nA,a0,a1);
        threefry(k0,k1,0u,nA + (uint32_t)(128*SC),c0,c1);
        uint32_t bitsH[2] = { a0^a1, c0^c1 };
#pragma unroll
        for (int half = 0; half < 2; half++) {
          int b = b0 + half*128;
          size_t li = (size_t)(256+b)*SC + s*C + lane;
          float lg = ((g_lp[li] + g_lp[PBL+li]) + (g_lp[2*PBL+li] + g_lp[3*PBL+li]))
                     + b3[s*C + lane];
          out_post[((size_t)b*T+t)*SC + s*C + lane] = lg;
          float m = lg;
          for (int o = 16; o; o >>= 1) m = fmaxf(m, __shfl_xor_sync(~0u, m, o));
          float e = expf(lg - m), sum = e;
          for (int o = 16; o; o >>= 1) sum += __shfl_xor_sync(~0u, sum, o);
          float p = 0.99f*(e/sum) + UNIADD;
          float uf = __uint_as_float((bitsH[half]>>9) | 0x3f800000u) - 1.0f;
          uf = fmaxf(uf + TINYF, TINYF);
          float val = -logf(-logf(uf)) + logf(p);
          float bv = val; int bidx = lane;
          for (int o = 16; o; o >>= 1) {
            float ov = __shfl_xor_sync(~0u, bv, o);
            int   oi = __shfl_xor_sync(~0u, bidx, o);
            if (ov > bv || (ov == bv && oi < bidx)) { bv = ov; bidx = oi; }
          }
          float oneh = (lane == bidx) ? 1.0f : 0.0f;
          out_stoch[((size_t)b*T+t)*SC + s*C + lane] = oneh;
          if (t + 1 < T)
            g_xin[(size_t)b*INX + s*C + lane] = isf[(size_t)b*T + t + 1] ? 0.0f : oneh;
        }
      }
      if (t + 1 < T)
        for (int i = gtid; i < B*A_; i += gstep) {
          int b = i>>5, a = i & 31;
          g_xin[(size_t)b*INX + SC + a] = actions[((size_t)b*T + t + 1)*A_ + a];
        }
    }
    gridbar();
  }
#undef POP
}

extern "C" void kernel_launch(void* const* d_in, const int* in_sizes, int n_in,
                              void* d_out, int out_size) {
  const float* embed  =(const float*)d_in[0];
  const float* actions=(const float*)d_in[1];
  const int*   isf    =(const int*)  d_in[2];
  const float* W_in =(const float*)d_in[5],  *b_in =(const float*)d_in[6];
  const float* W_blk=(const float*)d_in[7],  *b_blk=(const float*)d_in[8];
  const float* W_ih =(const float*)d_in[9],  *b_ih =(const float*)d_in[10];
  const float* W_hh =(const float*)d_in[11], *b_hh =(const float*)d_in[12];
  const float* W1   =(const float*)d_in[13], *b1   =(const float*)d_in[14];
  const float* W2   =(const float*)d_in[15], *b2   =(const float*)d_in[16];
  const float* W3   =(const float*)d_in[17], *b3   =(const float*)d_in[18];
  const float* W_proj=(const float*)d_in[19],*b_proj=(const float*)d_in[20];

  float* out = (float*)d_out;
  float* out_deter = out;                          // [B,T,D]
  float* out_stoch = out + (size_t)B*T*D;          // [B,T,S,C]
  float* out_prior = out_stoch + (size_t)B*T*SC;   // [B,T,S,C]
  float* out_post  = out_prior + (size_t)B*T*SC;   // [B,T,S,C]

  k_rssm<<<NBLK, NTH>>>(embed, actions, isf,
                        W_in, b_in, W_blk, b_blk, W_ih, b_ih, W_hh, b_hh,
                        W1, b1, W2, b2, W3, b3, W_proj, b_proj,
                        out_deter, out_stoch, out_prior, out_post);
}

// round 13
// speedup vs baseline: 1.8121x; 1.8121x over previous
#include <cuda_runtime.h>
#include <cstdint>
#include <cstddef>

constexpr int B=256, T=64, H=512, S=32, C=32, A_=32, E=1024, BS=256;
constexpr int D=2048, X3H=1536, INX=1056, G3=768, NG=6144, DE_IN=3072, SC=1024;
constexpr int NBLK=296, NTH=256;

__device__ __align__(16) float g_deter[B*D];
__device__ __align__(16) float g_WinT [INX*X3H];  // W_in transposed [c][j]
__device__ __align__(16) float g_x   [B*X3H];     // x final (silu'd, biased)
__device__ int   g_sidx[B*S];                     // sampled idx (-1 = masked)
__device__ __align__(16) float g_hp  [4*B*D];     // h partials NEXT step (split4, masked)
__device__ __align__(16) float g_gip [3*B*NG];    // gi partials (split3, raw)
__device__ __align__(16) float g_gh  [B*NG];      // gh (biased)
__device__ __align__(16) float g_dein[B*DE_IN];
__device__ __align__(16) float g_dp  [6*B*D];     // de partials (split6, raw)
__device__ __align__(16) float g_h1  [4*2*B*H];   // M=512 (prior|post), split4 raw
__device__ __align__(16) float g_h2  [4*2*B*H];   // split4 raw
__device__ __align__(16) float g_lp  [4*2*B*SC];  // logits partials (split4 raw)
__device__ unsigned g_cnt;
__device__ unsigned g_gen;
__device__ unsigned g_ctr[6*T];

// ----------------------------- grid barrier --------------------------------
__device__ __forceinline__ void gridbar() {
  __syncthreads();
  if (threadIdx.x == 0) {
    unsigned gen = *(volatile unsigned*)&g_gen;
    __threadfence();
    if (atomicAdd(&g_cnt, 1u) == gridDim.x - 1u) {
      g_cnt = 0u;
      __threadfence();
      atomicExch(&g_gen, gen + 1u);
    } else {
      while (*(volatile unsigned*)&g_gen == gen) {}
    }
    __threadfence();
  }
  __syncthreads();
}

// ------------------------------ threefry2x32 -------------------------------
__device__ __forceinline__ void threefry(uint32_t k0, uint32_t k1, uint32_t x0,
                                         uint32_t x1, uint32_t& o0, uint32_t& o1) {
  uint32_t ks2 = 0x1BD11BDAu ^ k0 ^ k1;
#define TFR(x,r) x = (x<<r)|(x>>(32-r))
#define TF4(a,b,c,d) x0+=x1;TFR(x1,a);x1^=x0; x0+=x1;TFR(x1,b);x1^=x0; x0+=x1;TFR(x1,c);x1^=x0; x0+=x1;TFR(x1,d);x1^=x0;
  x0 += k0; x1 += k1;
  TF4(13,15,26,6);  x0 += k1;  x1 += ks2 + 1u;
  TF4(17,29,16,24); x0 += ks2; x1 += k0 + 2u;
  TF4(13,15,26,6);  x0 += k0;  x1 += k1 + 3u;
  TF4(17,29,16,24); x0 += k1;  x1 += ks2 + 4u;
  TF4(13,15,26,6);  x0 += ks2; x1 += k0 + 5u;
  o0 = x0; o1 = x1;
#undef TF4
#undef TFR
}

__device__ __forceinline__ float silu1(float v) { return v/(1.0f+expf(-v)); }

// ------------------------------ GEMM tile 128x64 ---------------------------
// C[m0..m0+128, n0..n0+64) (+)= Aeff[:,kbase..+IN2) @ W[n,kbase..+IN2)^T
// Aeff: NP=1 plain A0; NP>=2: (sum of NP partials)+Abias, optional SiLU.
// 256 threads, per-thread 8 rows x 4 cols. WMODE 0:+bias; 1:raw.
template <int NP,int SILU,int WMODE,int MASKED>
__device__ __forceinline__ void gemm(
    const float* __restrict__ A0, size_t pstr,
    const float* __restrict__ Abias, int lda,
    const float* __restrict__ W, int ldw, const float* __restrict__ bias,
    float* __restrict__ Cb, int ldc,
    int IN2, int kbase, int m0, int n0, int aColBase,
    const int* __restrict__ isf, int mt,
    float (*As)[136], float (*Ws)[68], float* mrow) {
  const int tid = threadIdx.x;
  if (MASKED) { if (tid < 128) mrow[tid] = isf[(size_t)(m0+tid)*T + mt] ? 0.0f : 1.0f; }
  __syncthreads();
  const int aoff = aColBase + kbase;
  const float* Ab0 = A0 + (size_t)m0*lda + aoff;
  const float* Wb  = W + (size_t)n0*ldw + kbase;
  const int alr = tid>>1, alq = (tid&1)<<3;    // a: row 0..127, kcol 0/8
  const int wlr = tid>>2, wlq = (tid&3)<<2;    // w: row 0..63,  kcol 0..12
  const int ty = tid>>4, tx = tid&15;          // out: 8 rows, 4 cols
  float acc[8][4] = {};
  for (int k0 = 0; k0 < IN2; k0 += 16) {
    size_t ao = (size_t)alr*lda + k0 + alq;
    float4 av0 = *(const float4*)(Ab0 + ao);
    float4 av1 = *(const float4*)(Ab0 + ao + 4);
    if (NP>=2) {
#pragma unroll
      for (int p = 1; p < NP; p++) {
        float4 b0v = *(const float4*)(Ab0 + p*pstr + ao);
        float4 b1v = *(const float4*)(Ab0 + p*pstr + ao + 4);
        av0.x += b0v.x; av0.y += b0v.y; av0.z += b0v.z; av0.w += b0v.w;
        av1.x += b1v.x; av1.y += b1v.y; av1.z += b1v.z; av1.w += b1v.w;
      }
      float4 ab0 = *(const float4*)(Abias + aoff + k0 + alq);
      float4 ab1 = *(const float4*)(Abias + aoff + k0 + alq + 4);
      av0.x += ab0.x; av0.y += ab0.y; av0.z += ab0.z; av0.w += ab0.w;
      av1.x += ab1.x; av1.y += ab1.y; av1.z += ab1.z; av1.w += ab1.w;
      if (SILU) {
        av0.x=silu1(av0.x); av0.y=silu1(av0.y); av0.z=silu1(av0.z); av0.w=silu1(av0.w);
        av1.x=silu1(av1.x); av1.y=silu1(av1.y); av1.z=silu1(av1.z); av1.w=silu1(av1.w);
      }
    }
    if (MASKED) {
      float mm = mrow[alr];
      av0.x*=mm; av0.y*=mm; av0.z*=mm; av0.w*=mm;
      av1.x*=mm; av1.y*=mm; av1.z*=mm; av1.w*=mm;
    }
    As[alq+0][alr]=av0.x; As[alq+1][alr]=av0.y; As[alq+2][alr]=av0.z; As[alq+3][alr]=av0.w;
    As[alq+4][alr]=av1.x; As[alq+5][alr]=av1.y; As[alq+6][alr]=av1.z; As[alq+7][alr]=av1.w;
    float4 wv = *(const float4*)(Wb + (size_t)wlr*ldw + k0 + wlq);
    Ws[wlq+0][wlr]=wv.x; Ws[wlq+1][wlr]=wv.y; Ws[wlq+2][wlr]=wv.z; Ws[wlq+3][wlr]=wv.w;
    __syncthreads();
#pragma unroll
    for (int kk = 0; kk < 16; kk++) {
      float4 a0 = *(const float4*)&As[kk][ty<<3];
      float4 a1 = *(const float4*)&As[kk][(ty<<3)+4];
      float4 w  = *(const float4*)&Ws[kk][tx<<2];
      float am[8] = {a0.x,a0.y,a0.z,a0.w,a1.x,a1.y,a1.z,a1.w};
#pragma unroll
      for (int r = 0; r < 8; r++) {
        acc[r][0]+=am[r]*w.x; acc[r][1]+=am[r]*w.y;
        acc[r][2]+=am[r]*w.z; acc[r][3]+=am[r]*w.w;
      }
    }
    __syncthreads();
  }
#pragma unroll
  for (int r = 0; r < 8; r++) {
    int mi = m0 + (ty<<3) + r;
    int nb = n0 + (tx<<2);
    float4 v;
    v.x=acc[r][0]; v.y=acc[r][1]; v.z=acc[r][2]; v.w=acc[r][3];
    if (WMODE==0) {
      float4 bv = *(const float4*)(bias + nb);
      v.x+=bv.x; v.y+=bv.y; v.z+=bv.z; v.w+=bv.w;
    }
    *(float4*)(Cb + (size_t)mi*ldc + nb) = v;
  }
}

// ------------------------------ megakernel ---------------------------------
__global__ void __launch_bounds__(NTH, 2) k_rssm(
    const float* __restrict__ embed, const float* __restrict__ actions,
    const int* __restrict__ isf,
    const float* __restrict__ W_in,  const float* __restrict__ b_in,
    const float* __restrict__ W_blk, const float* __restrict__ b_blk,
    const float* __restrict__ W_ih,  const float* __restrict__ b_ih,
    const float* __restrict__ W_hh,  const float* __restrict__ b_hh,
    const float* __restrict__ W1,    const float* __restrict__ b1,
    const float* __restrict__ W2,    const float* __restrict__ b2,
    const float* __restrict__ W3,    const float* __restrict__ b3,
    const float* __restrict__ W_proj,const float* __restrict__ b_proj,
    float* __restrict__ out_deter, float* __restrict__ out_stoch,
    float* __restrict__ out_prior, float* __restrict__ out_post) {
  __shared__ __align__(16) float As[16][136];
  __shared__ __align__(16) float Ws[16][68];
  __shared__ float mrow[128];
  __shared__ int s_tl;
  const int bid = blockIdx.x;
  const int tid = threadIdx.x;
  const int gtid = bid*NTH + tid;
  const int gstep = gridDim.x*NTH;
  const int nwarp = gridDim.x*(NTH/32);
  const int wid = bid*(NTH/32) + (tid>>5);
  const int lane = tid & 31;
  const float TINYF = 1.17549435e-38f;
  const float UNIADD = (float)(0.01/32.0);
  const size_t PBD = (size_t)B*D;
  const size_t PBG = (size_t)B*NG;
  const size_t PBH = (size_t)2*B*H;
  const size_t PBL = (size_t)2*B*SC;

#define POP(pid) ({ if (tid==0) s_tl = (int)atomicAdd(&g_ctr[pid], 1u); \
                    __syncthreads(); int _v = s_tl; _v; })

  for (int i = gtid; i < 6*T; i += gstep) g_ctr[i] = 0u;
  for (int i = gtid; i < B*D; i += gstep) g_deter[i] = 0.0f;
  for (size_t i = gtid; i < 4*PBD; i += gstep) g_hp[i] = 0.0f;   // h for t=0 (deter0=0)
  for (int i = gtid; i < B*S; i += gstep) g_sidx[i] = -1;        // stoch0 = 0
  for (size_t i = gtid; i < (size_t)INX*X3H; i += gstep) {       // W_in transpose
    int c = (int)(i / X3H), j = (int)(i - (size_t)c*X3H);
    g_WinT[i] = W_in[(size_t)j*INX + c];
  }
  gridbar();

  for (int t = 0; t < T; t++) {
    const int hlive = (t + 1 < T) ? 1 : 0;
    // P1a: x = silu(b_in + gather(one-hot cols) + W_in_act@action)   [direct]
    for (int q = gtid; q < B*(X3H/4); q += gstep) {
      int b = q/(X3H/4), j = (q - b*(X3H/4))*4;
      float4 acc = *(const float4*)(b_in + j);
      const int* idxp = g_sidx + b*S;
#pragma unroll 4
      for (int s = 0; s < S; s++) {
        int c = idxp[s];
        if (c >= 0) {
          float4 wv = *(const float4*)(g_WinT + (size_t)(s*C + c)*X3H + j);
          acc.x+=wv.x; acc.y+=wv.y; acc.z+=wv.z; acc.w+=wv.w;
        }
      }
      const float* act = actions + ((size_t)b*T + t)*A_;
#pragma unroll 4
      for (int a = 0; a < A_; a++) {
        float fa = act[a];
        float4 wv = *(const float4*)(g_WinT + (size_t)(SC + a)*X3H + j);
        acc.x+=fa*wv.x; acc.y+=fa*wv.y; acc.z+=fa*wv.z; acc.w+=fa*wv.w;
      }
      acc.x=silu1(acc.x); acc.y=silu1(acc.y); acc.z=silu1(acc.z); acc.w=silu1(acc.w);
      *(float4*)(g_x + (size_t)b*X3H + j) = acc;
    }
    // P1b: gh = (sum4 hp + b_blk)@W_hh + b_hh  (192 tiles x 16ch, blockdiag)
    for (;;) {
      int tl = POP(t*6+0); if (tl >= 192) break;
      int n0 = (tl%96)<<6;
      gemm<4,0,0,0>(g_hp, PBD, b_blk, D, W_hh, BS, b_hh,
                    g_gh, NG, BS, 0,
                    (tl/96)<<7, n0, (n0/G3)*BS, 0, 0, As, Ws, mrow);
    }
    gridbar();
    // P2: gi partials = x@W_ih  (split3: 576 tiles x 32ch)
    for (;;) {
      int tl = POP(t*6+1); if (tl >= 576) break;
      int p = tl/192, i = tl%192;
      gemm<1,0,1,0>(g_x, 0, 0, X3H, W_ih, X3H, 0,
                    g_gip + p*PBG, NG, X3H/3, p*(X3H/3),
                    (i/96)<<7, (i%96)<<6, 0, 0, 0, As, Ws, mrow);
    }
    gridbar();
    // P3: GRU combine -> deter/out_deter/dein ; embed -> dein
    for (int i = gtid; i < B*D; i += gstep) {
      int b = i>>11, d = i & (D-1), k = d>>8, g = d & (BS-1);
      size_t base = (size_t)b*NG + k*G3 + g;
      float ir = (g_gip[base]      + g_gip[PBG+base])      + g_gip[2*PBG+base]      + b_ih[k*G3+g];
      float iz = (g_gip[base+BS]   + g_gip[PBG+base+BS])   + g_gip[2*PBG+base+BS]   + b_ih[k*G3+g+BS];
      float inn= (g_gip[base+2*BS] + g_gip[PBG+base+2*BS]) + g_gip[2*PBG+base+2*BS] + b_ih[k*G3+g+2*BS];
      float hr=g_gh[base], hz=g_gh[base+BS], hnn=g_gh[base+2*BS];
      float hv = ((g_hp[i] + g_hp[PBD+i]) + (g_hp[2*PBD+i] + g_hp[3*PBD+i])) + b_blk[d];
      float r = 1.0f/(1.0f+expf(-(ir+hr)));
      float z = 1.0f/(1.0f+expf(-(iz+hz)));
      float n = tanhf(inn + r*hnn);
      float dv = (1.0f - z)*n + z*hv;
      g_deter[i] = dv;
      g_dein[(size_t)b*DE_IN + d] = dv;
      out_deter[((size_t)b*T+t)*D + d] = dv;
    }
    for (int i = gtid; i < B*E; i += gstep) {
      int b = i>>10, j = i & (E-1);
      g_dein[(size_t)b*DE_IN + D + j] = embed[((size_t)b*T+t)*E + j];
    }
    gridbar();
    // P4: de partials (dein@W_proj, split6: 384 tiles x 32ch)
    //     h01 partials next step (masked deter@W_blk, split4 p=0,1: 128 x 32ch)
    {
      int nP4 = 384 + hlive*128;
      for (;;) {
        int tl = POP(t*6+2); if (tl >= nP4) break;
        if (tl < 384) {
          int p = tl/64, i = tl%64;
          gemm<1,0,1,0>(g_dein, 0, 0, DE_IN, W_proj, DE_IN, 0,
                        g_dp + p*PBD, D, DE_IN/6, p*(DE_IN/6),
                        (i/32)<<7, (i%32)<<6, 0, 0, 0, As, Ws, mrow);
        } else {
          int j = tl-384, p = j/64, i = j%64;
          gemm<1,0,1,1>(g_deter, 0, 0, D, W_blk, D, 0,
                        g_hp + p*PBD, D, D/4, p*(D/4),
                        (i/32)<<7, (i%32)<<6, 0, isf, t+1, As, Ws, mrow);
        }
      }
    }
    gridbar();
    // P5: h1 partials, M=512 ([deter | de-combine6+b_proj])@W1, split4: 128 x 32ch
    //     h23 partials next step (p=2,3: 128 x 32ch)
    {
      int nP5 = 128 + hlive*128;
      for (;;) {
        int tl = POP(t*6+3); if (tl >= nP5) break;
        if (tl < 128) {
          int p = tl/32, i = tl%32;
          int m0 = (i/8)<<7, n0 = (i%8)<<6;
          float* Cp = g_h1 + p*PBH;
          if (m0 < 256)
            gemm<1,0,1,0>(g_deter, 0, 0, D, W1, D, 0, Cp, H,
                          D/4, p*(D/4), m0, n0, 0, 0, 0, As, Ws, mrow);
          else
            gemm<6,0,1,0>(g_dp - (size_t)256*D, PBD, b_proj, D, W1, D, 0,
                          Cp, H, D/4, p*(D/4), m0, n0, 0, 0, 0, As, Ws, mrow);
        } else {
          int j = tl-128, p = 2 + j/64, i = j%64;
          gemm<1,0,1,1>(g_deter, 0, 0, D, W_blk, D, 0,
                        g_hp + p*PBD, D, D/4, p*(D/4),
                        (i/32)<<7, (i%32)<<6, 0, isf, t+1, As, Ws, mrow);
        }
      }
    }
    gridbar();
    // P6: h2 partials = silu(h1-combine4 + b1)@W2, M=512, split4: 128 x 8ch
    for (;;) {
      int tl = POP(t*6+4); if (tl >= 128) break;
      int p = tl/32, i = tl%32;
      gemm<4,1,1,0>(g_h1, PBH, b1, H, W2, H, 0,
                    g_h2 + p*PBH, H, H/4, p*(H/4),
                    (i/8)<<7, (i%8)<<6, 0, 0, 0, As, Ws, mrow);
    }
    gridbar();
    // P7: logit partials = silu(h2-combine4 + b2)@W3, M=512, split4: 256 x 8ch
    for (;;) {
      int tl = POP(t*6+5); if (tl >= 256) break;
      int p = tl/64, i = tl%64;
      gemm<4,1,1,0>(g_h2, PBH, b2, H, W3, H, 0,
                    g_lp + p*PBL, SC, H/4, p*(H/4),
                    (i/16)<<7, (i%16)<<6, 0, 0, 0, As, Ws, mrow);
    }
    gridbar();
    // P8: prior combine -> out_prior ; sample(post combine) -> out_post/stoch/sidx
    for (int i = gtid; i < B*SC; i += gstep) {
      int b = i>>10, j = i & (SC-1);
      out_prior[((size_t)b*T+t)*SC + j] =
        ((g_lp[i] + g_lp[PBL+i]) + (g_lp[2*PBL+i] + g_lp[3*PBL+i])) + b3[j];
    }
    {
      uint32_t k0, k1;
      threefry(0u, 42u, 0u, (uint32_t)t, k0, k1);   // fold_in(key(42), t)
      for (int gw = wid; gw < 128*32; gw += nwarp) {
        int b0 = gw >> 5, s = gw & 31;
        uint32_t nA = (uint32_t)(b0*SC + s*C + lane);
        uint32_t a0,a1,c0,c1;
        threefry(k0,k1,0u,nA,a0,a1);
        threefry(k0,k1,0u,nA + (uint32_t)(128*SC),c0,c1);
        uint32_t bitsH[2] = { a0^a1, c0^c1 };
#pragma unroll
        for (int half = 0; half < 2; half++) {
          int b = b0 + half*128;
          size_t li = (size_t)(256+b)*SC + s*C + lane;
          float lg = ((g_lp[li] + g_lp[PBL+li]) + (g_lp[2*PBL+li] + g_lp[3*PBL+li]))
                     + b3[s*C + lane];
          out_post[((size_t)b*T+t)*SC + s*C + lane] = lg;
          float m = lg;
          for (int o = 16; o; o >>= 1) m = fmaxf(m, __shfl_xor_sync(~0u, m, o));
          float e = expf(lg - m), sum = e;
          for (int o = 16; o; o >>= 1) sum += __shfl_xor_sync(~0u, sum, o);
          float p = 0.99f*(e/sum) + UNIADD;
          float uf = __uint_as_float((bitsH[half]>>9) | 0x3f800000u) - 1.0f;
          uf = fmaxf(uf + TINYF, TINYF);
          float val = -logf(-logf(uf)) + logf(p);
          float bv = val; int bidx = lane;
          for (int o = 16; o; o >>= 1) {
            float ov = __shfl_xor_sync(~0u, bv, o);
            int   oi = __shfl_xor_sync(~0u, bidx, o);
            if (ov > bv || (ov == bv && oi < bidx)) { bv = ov; bidx = oi; }
          }
          float oneh = (lane == bidx) ? 1.0f : 0.0f;
          out_stoch[((size_t)b*T+t)*SC + s*C + lane] = oneh;
          if (lane == 0 && t + 1 < T)
            g_sidx[(size_t)b*S + s] = isf[(size_t)b*T + t + 1] ? -1 : bidx;
        }
      }
    }
    gridbar();
  }
#undef POP
}

extern "C" void kernel_launch(void* const* d_in, const int* in_sizes, int n_in,
                              void* d_out, int out_size) {
  const float* embed  =(const float*)d_in[0];
  const float* actions=(const float*)d_in[1];
  const int*   isf    =(const int*)  d_in[2];
  const float* W_in =(const float*)d_in[5],  *b_in =(const float*)d_in[6];
  const float* W_blk=(const float*)d_in[7],  *b_blk=(const float*)d_in[8];
  const float* W_ih =(const float*)d_in[9],  *b_ih =(const float*)d_in[10];
  const float* W_hh =(const float*)d_in[11], *b_hh =(const float*)d_in[12];
  const float* W1   =(const float*)d_in[13], *b1   =(const float*)d_in[14];
  const float* W2   =(const float*)d_in[15], *b2   =(const float*)d_in[16];
  const float* W3   =(const float*)d_in[17], *b3   =(const float*)d_in[18];
  const float* W_proj=(const float*)d_in[19],*b_proj=(const float*)d_in[20];

  float* out = (float*)d_out;
  float* out_deter = out;                          // [B,T,D]
  float* out_stoch = out + (size_t)B*T*D;          // [B,T,S,C]
  float* out_prior = out_stoch + (size_t)B*T*SC;   // [B,T,S,C]
  float* out_post  = out_prior + (size_t)B*T*SC;   // [B,T,S,C]

  k_rssm<<<NBLK, NTH>>>(embed, actions, isf,
                        W_in, b_in, W_blk, b_blk, W_ih, b_ih, W_hh, b_hh,
                        W1, b1, W2, b2, W3, b3, W_proj, b_proj,
                        out_deter, out_stoch, out_prior, out_post);
}

// round 14
// speedup vs baseline: 1.9147x; 1.0566x over previous
#include <cuda_runtime.h>
#include <cstdint>
#include <cstddef>

constexpr int B=256, T=64, H=512, S=32, C=32, A_=32, E=1024, BS=256;
constexpr int D=2048, X3H=1536, INX=1056, G3=768, NG=6144, DE_IN=3072, SC=1024;
constexpr int NBLK=296, NTH=256;

__device__ __align__(16) float g_deter[B*D];
__device__ __align__(16) float g_WinT [INX*X3H];  // W_in transposed [c][j]
__device__ __align__(16) float g_x   [B*X3H];     // x final (silu'd, biased)
__device__ int   g_sidx[B*S];                     // sampled idx (-1 = masked)
__device__ __align__(16) float g_hp  [4*B*D];     // h partials NEXT step (split4, masked)
__device__ __align__(16) float g_gip [3*B*NG];    // gi partials (split3, raw)
__device__ __align__(16) float g_gh  [B*NG];      // gh (biased)
__device__ __align__(16) float g_dein[B*DE_IN];
__device__ __align__(16) float g_dp  [6*B*D];     // de partials (split6, raw)
__device__ __align__(16) float g_h1  [4*2*B*H];   // M=512 (prior|post), split4 raw
__device__ __align__(16) float g_h2  [4*2*B*H];   // split4 raw
__device__ __align__(16) float g_lp  [4*2*B*SC];  // logits partials (split4 raw)
__device__ unsigned g_cnt;
__device__ unsigned g_gen;
__device__ unsigned g_ctr[6*T];

// ----------------------------- grid barrier --------------------------------
__device__ __forceinline__ void gridbar() {
  __syncthreads();
  if (threadIdx.x == 0) {
    unsigned gen = *(volatile unsigned*)&g_gen;
    __threadfence();
    if (atomicAdd(&g_cnt, 1u) == gridDim.x - 1u) {
      g_cnt = 0u;
      __threadfence();
      atomicExch(&g_gen, gen + 1u);
    } else {
      while (*(volatile unsigned*)&g_gen == gen) {}
    }
    __threadfence();
  }
  __syncthreads();
}

// ------------------------------ threefry2x32 -------------------------------
__device__ __forceinline__ void threefry(uint32_t k0, uint32_t k1, uint32_t x0,
                                         uint32_t x1, uint32_t& o0, uint32_t& o1) {
  uint32_t ks2 = 0x1BD11BDAu ^ k0 ^ k1;
#define TFR(x,r) x = (x<<r)|(x>>(32-r))
#define TF4(a,b,c,d) x0+=x1;TFR(x1,a);x1^=x0; x0+=x1;TFR(x1,b);x1^=x0; x0+=x1;TFR(x1,c);x1^=x0; x0+=x1;TFR(x1,d);x1^=x0;
  x0 += k0; x1 += k1;
  TF4(13,15,26,6);  x0 += k1;  x1 += ks2 + 1u;
  TF4(17,29,16,24); x0 += ks2; x1 += k0 + 2u;
  TF4(13,15,26,6);  x0 += k0;  x1 += k1 + 3u;
  TF4(17,29,16,24); x0 += k1;  x1 += ks2 + 4u;
  TF4(13,15,26,6);  x0 += ks2; x1 += k0 + 5u;
  o0 = x0; o1 = x1;
#undef TF4
#undef TFR
}

__device__ __forceinline__ float silu1(float v) { return v/(1.0f+expf(-v)); }

// ------------------------------ GEMM tile 128x64 ---------------------------
// Double-buffered smem pipeline: one __syncthreads per 16-k chunk; next
// chunk's global loads + A-combine overlap with current chunk's FFMAs.
// Aeff: NP=1 plain A0; NP>=2: (sum of NP partials)+Abias, optional SiLU.
// 256 threads, per-thread 8 rows x 4 cols. WMODE 0:+bias; 1:raw.
template <int NP,int SILU,int WMODE,int MASKED>
__device__ __forceinline__ void gemm(
    const float* __restrict__ A0, size_t pstr,
    const float* __restrict__ Abias, int lda,
    const float* __restrict__ W, int ldw, const float* __restrict__ bias,
    float* __restrict__ Cb, int ldc,
    int IN2, int kbase, int m0, int n0, int aColBase,
    const int* __restrict__ isf, int mt,
    float (*As)[16][136], float (*Ws)[16][68], float* mrow) {
  const int tid = threadIdx.x;
  if (MASKED) { if (tid < 128) mrow[tid] = isf[(size_t)(m0+tid)*T + mt] ? 0.0f : 1.0f; }
  __syncthreads();   // mrow ready + protects smem reuse across tiles
  const int aoff = aColBase + kbase;
  const float* Ab0 = A0 + (size_t)m0*lda + aoff;
  const float* Wb  = W + (size_t)n0*ldw + kbase;
  const int alr = tid>>1, alq = (tid&1)<<3;    // a: row 0..127, kcol 0/8
  const int wlr = tid>>2, wlq = (tid&3)<<2;    // w: row 0..63,  kcol 0..12
  const int ty = tid>>4, tx = tid&15;          // out: 8 rows, 4 cols
  float acc[8][4] = {};
  float4 av0, av1, wv;

#define LOADCHUNK(KO) do {                                                   \
    size_t ao = (size_t)alr*lda + (KO) + alq;                                \
    av0 = *(const float4*)(Ab0 + ao);                                        \
    av1 = *(const float4*)(Ab0 + ao + 4);                                    \
    if (NP>=2) {                                                             \
      _Pragma("unroll")                                                      \
      for (int p = 1; p < NP; p++) {                                         \
        float4 b0v = *(const float4*)(Ab0 + p*pstr + ao);                    \
        float4 b1v = *(const float4*)(Ab0 + p*pstr + ao + 4);                \
        av0.x += b0v.x; av0.y += b0v.y; av0.z += b0v.z; av0.w += b0v.w;      \
        av1.x += b1v.x; av1.y += b1v.y; av1.z += b1v.z; av1.w += b1v.w;      \
      }                                                                      \
      float4 ab0 = *(const float4*)(Abias + aoff + (KO) + alq);              \
      float4 ab1 = *(const float4*)(Abias + aoff + (KO) + alq + 4);          \
      av0.x += ab0.x; av0.y += ab0.y; av0.z += ab0.z; av0.w += ab0.w;        \
      av1.x += ab1.x; av1.y += ab1.y; av1.z += ab1.z; av1.w += ab1.w;        \
      if (SILU) {                                                            \
        av0.x=silu1(av0.x); av0.y=silu1(av0.y);                              \
        av0.z=silu1(av0.z); av0.w=silu1(av0.w);                              \
        av1.x=silu1(av1.x); av1.y=silu1(av1.y);                              \
        av1.z=silu1(av1.z); av1.w=silu1(av1.w);                              \
      }                                                                      \
    }                                                                        \
    if (MASKED) {                                                            \
      float mm = mrow[alr];                                                  \
      av0.x*=mm; av0.y*=mm; av0.z*=mm; av0.w*=mm;                            \
      av1.x*=mm; av1.y*=mm; av1.z*=mm; av1.w*=mm;                            \
    }                                                                        \
    wv = *(const float4*)(Wb + (size_t)wlr*ldw + (KO) + wlq);                \
  } while(0)

#define STORECHUNK(BUF) do {                                                 \
    As[BUF][alq+0][alr]=av0.x; As[BUF][alq+1][alr]=av0.y;                    \
    As[BUF][alq+2][alr]=av0.z; As[BUF][alq+3][alr]=av0.w;                    \
    As[BUF][alq+4][alr]=av1.x; As[BUF][alq+5][alr]=av1.y;                    \
    As[BUF][alq+6][alr]=av1.z; As[BUF][alq+7][alr]=av1.w;                    \
    Ws[BUF][wlq+0][wlr]=wv.x; Ws[BUF][wlq+1][wlr]=wv.y;                      \
    Ws[BUF][wlq+2][wlr]=wv.z; Ws[BUF][wlq+3][wlr]=wv.w;                      \
  } while(0)

  LOADCHUNK(0);
  STORECHUNK(0);
  __syncthreads();
  int buf = 0;
  for (int k0 = 0; k0 < IN2; k0 += 16) {
    const bool more = (k0 + 16 < IN2);
    if (more) LOADCHUNK(k0 + 16);
#pragma unroll
    for (int kk = 0; kk < 16; kk++) {
      float4 a0 = *(const float4*)&As[buf][kk][ty<<3];
      float4 a1 = *(const float4*)&As[buf][kk][(ty<<3)+4];
      float4 w  = *(const float4*)&Ws[buf][kk][tx<<2];
      float am[8] = {a0.x,a0.y,a0.z,a0.w,a1.x,a1.y,a1.z,a1.w};
#pragma unroll
      for (int r = 0; r < 8; r++) {
        acc[r][0]+=am[r]*w.x; acc[r][1]+=am[r]*w.y;
        acc[r][2]+=am[r]*w.z; acc[r][3]+=am[r]*w.w;
      }
    }
    if (more) STORECHUNK(buf^1);
    __syncthreads();
    buf ^= 1;
  }
#undef LOADCHUNK
#undef STORECHUNK
#pragma unroll
  for (int r = 0; r < 8; r++) {
    int mi = m0 + (ty<<3) + r;
    int nb = n0 + (tx<<2);
    float4 v;
    v.x=acc[r][0]; v.y=acc[r][1]; v.z=acc[r][2]; v.w=acc[r][3];
    if (WMODE==0) {
      float4 bv = *(const float4*)(bias + nb);
      v.x+=bv.x; v.y+=bv.y; v.z+=bv.z; v.w+=bv.w;
    }
    *(float4*)(Cb + (size_t)mi*ldc + nb) = v;
  }
}

// ------------------------------ megakernel ---------------------------------
__global__ void __launch_bounds__(NTH, 2) k_rssm(
    const float* __restrict__ embed, const float* __restrict__ actions,
    const int* __restrict__ isf,
    const float* __restrict__ W_in,  const float* __restrict__ b_in,
    const float* __restrict__ W_blk, const float* __restrict__ b_blk,
    const float* __restrict__ W_ih,  const float* __restrict__ b_ih,
    const float* __restrict__ W_hh,  const float* __restrict__ b_hh,
    const float* __restrict__ W1,    const float* __restrict__ b1,
    const float* __restrict__ W2,    const float* __restrict__ b2,
    const float* __restrict__ W3,    const float* __restrict__ b3,
    const float* __restrict__ W_proj,const float* __restrict__ b_proj,
    float* __restrict__ out_deter, float* __restrict__ out_stoch,
    float* __restrict__ out_prior, float* __restrict__ out_post) {
  __shared__ __align__(16) float As[2][16][136];
  __shared__ __align__(16) float Ws[2][16][68];
  __shared__ float mrow[128];
  __shared__ int s_tl;
  const int bid = blockIdx.x;
  const int tid = threadIdx.x;
  const int gtid = bid*NTH + tid;
  const int gstep = gridDim.x*NTH;
  const int nwarp = gridDim.x*(NTH/32);
  const int wid = bid*(NTH/32) + (tid>>5);
  const int lane = tid & 31;
  const float TINYF = 1.17549435e-38f;
  const float UNIADD = (float)(0.01/32.0);
  const size_t PBD = (size_t)B*D;
  const size_t PBG = (size_t)B*NG;
  const size_t PBH = (size_t)2*B*H;
  const size_t PBL = (size_t)2*B*SC;

#define POP(pid) ({ if (tid==0) s_tl = (int)atomicAdd(&g_ctr[pid], 1u); \
                    __syncthreads(); int _v = s_tl; _v; })

  for (int i = gtid; i < 6*T; i += gstep) g_ctr[i] = 0u;
  for (int i = gtid; i < B*D; i += gstep) g_deter[i] = 0.0f;
  for (size_t i = gtid; i < 4*PBD; i += gstep) g_hp[i] = 0.0f;   // h for t=0 (deter0=0)
  for (int i = gtid; i < B*S; i += gstep) g_sidx[i] = -1;        // stoch0 = 0
  for (size_t i = gtid; i < (size_t)INX*X3H; i += gstep) {       // W_in transpose
    int c = (int)(i / X3H), j = (int)(i - (size_t)c*X3H);
    g_WinT[i] = W_in[(size_t)j*INX + c];
  }
  gridbar();

  for (int t = 0; t < T; t++) {
    const int hlive = (t + 1 < T) ? 1 : 0;
    // P1a: x = silu(b_in + gather(one-hot cols) + W_in_act@action)   [direct]
    for (int q = gtid; q < B*(X3H/4); q += gstep) {
      int b = q/(X3H/4), j = (q - b*(X3H/4))*4;
      float4 acc = *(const float4*)(b_in + j);
      const int* idxp = g_sidx + b*S;
#pragma unroll 4
      for (int s = 0; s < S; s++) {
        int c = idxp[s];
        if (c >= 0) {
          float4 wv = *(const float4*)(g_WinT + (size_t)(s*C + c)*X3H + j);
          acc.x+=wv.x; acc.y+=wv.y; acc.z+=wv.z; acc.w+=wv.w;
        }
      }
      const float* act = actions + ((size_t)b*T + t)*A_;
#pragma unroll 4
      for (int a = 0; a < A_; a++) {
        float fa = act[a];
        float4 wv = *(const float4*)(g_WinT + (size_t)(SC + a)*X3H + j);
        acc.x+=fa*wv.x; acc.y+=fa*wv.y; acc.z+=fa*wv.z; acc.w+=fa*wv.w;
      }
      acc.x=silu1(acc.x); acc.y=silu1(acc.y); acc.z=silu1(acc.z); acc.w=silu1(acc.w);
      *(float4*)(g_x + (size_t)b*X3H + j) = acc;
    }
    // P1b: gh = (sum4 hp + b_blk)@W_hh + b_hh  (192 tiles x 16ch, blockdiag)
    for (;;) {
      int tl = POP(t*6+0); if (tl >= 192) break;
      int n0 = (tl%96)<<6;
      gemm<4,0,0,0>(g_hp, PBD, b_blk, D, W_hh, BS, b_hh,
                    g_gh, NG, BS, 0,
                    (tl/96)<<7, n0, (n0/G3)*BS, 0, 0, As, Ws, mrow);
    }
    gridbar();
    // P2: gi partials = x@W_ih  (split3: 576 tiles x 32ch)
    for (;;) {
      int tl = POP(t*6+1); if (tl >= 576) break;
      int p = tl/192, i = tl%192;
      gemm<1,0,1,0>(g_x, 0, 0, X3H, W_ih, X3H, 0,
                    g_gip + p*PBG, NG, X3H/3, p*(X3H/3),
                    (i/96)<<7, (i%96)<<6, 0, 0, 0, As, Ws, mrow);
    }
    gridbar();
    // P3: GRU combine -> deter/out_deter/dein ; embed -> dein
    for (int i = gtid; i < B*D; i += gstep) {
      int b = i>>11, d = i & (D-1), k = d>>8, g = d & (BS-1);
      size_t base = (size_t)b*NG + k*G3 + g;
      float ir = (g_gip[base]      + g_gip[PBG+base])      + g_gip[2*PBG+base]      + b_ih[k*G3+g];
      float iz = (g_gip[base+BS]   + g_gip[PBG+base+BS])   + g_gip[2*PBG+base+BS]   + b_ih[k*G3+g+BS];
      float inn= (g_gip[base+2*BS] + g_gip[PBG+base+2*BS]) + g_gip[2*PBG+base+2*BS] + b_ih[k*G3+g+2*BS];
      float hr=g_gh[base], hz=g_gh[base+BS], hnn=g_gh[base+2*BS];
      float hv = ((g_hp[i] + g_hp[PBD+i]) + (g_hp[2*PBD+i] + g_hp[3*PBD+i])) + b_blk[d];
      float r = 1.0f/(1.0f+expf(-(ir+hr)));
      float z = 1.0f/(1.0f+expf(-(iz+hz)));
      float n = tanhf(inn + r*hnn);
      float dv = (1.0f - z)*n + z*hv;
      g_deter[i] = dv;
      g_dein[(size_t)b*DE_IN + d] = dv;
      out_deter[((size_t)b*T+t)*D + d] = dv;
    }
    for (int i = gtid; i < B*E; i += gstep) {
      int b = i>>10, j = i & (E-1);
      g_dein[(size_t)b*DE_IN + D + j] = embed[((size_t)b*T+t)*E + j];
    }
    gridbar();
    // P4: de partials (dein@W_proj, split6: 384 tiles x 32ch)
    //     h01 partials next step (masked deter@W_blk, split4 p=0,1: 128 x 32ch)
    {
      int nP4 = 384 + hlive*128;
      for (;;) {
        int tl = POP(t*6+2); if (tl >= nP4) break;
        if (tl < 384) {
          int p = tl/64, i = tl%64;
          gemm<1,0,1,0>(g_dein, 0, 0, DE_IN, W_proj, DE_IN, 0,
                        g_dp + p*PBD, D, DE_IN/6, p*(DE_IN/6),
                        (i/32)<<7, (i%32)<<6, 0, 0, 0, As, Ws, mrow);
        } else {
          int j = tl-384, p = j/64, i = j%64;
          gemm<1,0,1,1>(g_deter, 0, 0, D, W_blk, D, 0,
                        g_hp + p*PBD, D, D/4, p*(D/4),
                        (i/32)<<7, (i%32)<<6, 0, isf, t+1, As, Ws, mrow);
        }
      }
    }
    gridbar();
    // P5: h1 partials, M=512 ([deter | de-combine6+b_proj])@W1, split4: 128 x 32ch
    //     h23 partials next step (p=2,3: 128 x 32ch)
    {
      int nP5 = 128 + hlive*128;
      for (;;) {
        int tl = POP(t*6+3); if (tl >= nP5) break;
        if (tl < 128) {
          int p = tl/32, i = tl%32;
          int m0 = (i/8)<<7, n0 = (i%8)<<6;
          float* Cp = g_h1 + p*PBH;
          if (m0 < 256)
            gemm<1,0,1,0>(g_deter, 0, 0, D, W1, D, 0, Cp, H,
                          D/4, p*(D/4), m0, n0, 0, 0, 0, As, Ws, mrow);
          else
            gemm<6,0,1,0>(g_dp - (size_t)256*D, PBD, b_proj, D, W1, D, 0,
                          Cp, H, D/4, p*(D/4), m0, n0, 0, 0, 0, As, Ws, mrow);
        } else {
          int j = tl-128, p = 2 + j/64, i = j%64;
          gemm<1,0,1,1>(g_deter, 0, 0, D, W_blk, D, 0,
                        g_hp + p*PBD, D, D/4, p*(D/4),
                        (i/32)<<7, (i%32)<<6, 0, isf, t+1, As, Ws, mrow);
        }
      }
    }
    gridbar();
    // P6: h2 partials = silu(h1-combine4 + b1)@W2, M=512, split4: 128 x 8ch
    for (;;) {
      int tl = POP(t*6+4); if (tl >= 128) break;
      int p = tl/32, i = tl%32;
      gemm<4,1,1,0>(g_h1, PBH, b1, H, W2, H, 0,
                    g_h2 + p*PBH, H, H/4, p*(H/4),
                    (i/8)<<7, (i%8)<<6, 0, 0, 0, As, Ws, mrow);
    }
    gridbar();
    // P7: logit partials = silu(h2-combine4 + b2)@W3, M=512, split4: 256 x 8ch
    for (;;) {
      int tl = POP(t*6+5); if (tl >= 256) break;
      int p = tl/64, i = tl%64;
      gemm<4,1,1,0>(g_h2, PBH, b2, H, W3, H, 0,
                    g_lp + p*PBL, SC, H/4, p*(H/4),
                    (i/16)<<7, (i%16)<<6, 0, 0, 0, As, Ws, mrow);
    }
    gridbar();
    // P8: prior combine -> out_prior ; sample(post combine) -> out_post/stoch/sidx
    for (int i = gtid; i < B*SC; i += gstep) {
      int b = i>>10, j = i & (SC-1);
      out_prior[((size_t)b*T+t)*SC + j] =
        ((g_lp[i] + g_lp[PBL+i]) + (g_lp[2*PBL+i] + g_lp[3*PBL+i])) + b3[j];
    }
    {
      uint32_t k0, k1;
      threefry(0u, 42u, 0u, (uint32_t)t, k0, k1);   // fold_in(key(42), t)
      for (int gw = wid; gw < 128*32; gw += nwarp) {
        int b0 = gw >> 5, s = gw & 31;
        uint32_t nA = (uint32_t)(b0*SC + s*C + lane);
        uint32_t a0,a1,c0,c1;
        threefry(k0,k1,0u,nA,a0,a1);
        threefry(k0,k1,0u,nA + (uint32_t)(128*SC),c0,c1);
        uint32_t bitsH[2] = { a0^a1, c0^c1 };
#pragma unroll
        for (int half = 0; half < 2; half++) {
          int b = b0 + half*128;
          size_t li = (size_t)(256+b)*SC + s*C + lane;
          float lg = ((g_lp[li] + g_lp[PBL+li]) + (g_lp[2*PBL+li] + g_lp[3*PBL+li]))
                     + b3[s*C + lane];
          out_post[((size_t)b*T+t)*SC + s*C + lane] = lg;
          float m = lg;
          for (int o = 16; o; o >>= 1) m = fmaxf(m, __shfl_xor_sync(~0u, m, o));
          float e = expf(lg - m), sum = e;
          for (int o = 16; o; o >>= 1) sum += __shfl_xor_sync(~0u, sum, o);
          float p = 0.99f*(e/sum) + UNIADD;
          float uf = __uint_as_float((bitsH[half]>>9) | 0x3f800000u) - 1.0f;
          uf = fmaxf(uf + TINYF, TINYF);
          float val = -logf(-logf(uf)) + logf(p);
          float bv = val; int bidx = lane;
          for (int o = 16; o; o >>= 1) {
            float ov = __shfl_xor_sync(~0u, bv, o);
            int   oi = __shfl_xor_sync(~0u, bidx, o);
            if (ov > bv || (ov == bv && oi < bidx)) { bv = ov; bidx = oi; }
          }
          float oneh = (lane == bidx) ? 1.0f : 0.0f;
          out_stoch[((size_t)b*T+t)*SC + s*C + lane] = oneh;
          if (lane == 0 && t + 1 < T)
            g_sidx[(size_t)b*S + s] = isf[(size_t)b*T + t + 1] ? -1 : bidx;
        }
      }
    }
    gridbar();
  }
#undef POP
}

extern "C" void kernel_launch(void* const* d_in, const int* in_sizes, int n_in,
                              void* d_out, int out_size) {
  const float* embed  =(const float*)d_in[0];
  const float* actions=(const float*)d_in[1];
  const int*   isf    =(const int*)  d_in[2];
  const float* W_in =(const float*)d_in[5],  *b_in =(const float*)d_in[6];
  const float* W_blk=(const float*)d_in[7],  *b_blk=(const float*)d_in[8];
  const float* W_ih =(const float*)d_in[9],  *b_ih =(const float*)d_in[10];
  const float* W_hh =(const float*)d_in[11], *b_hh =(const float*)d_in[12];
  const float* W1   =(const float*)d_in[13], *b1   =(const float*)d_in[14];
  const float* W2   =(const float*)d_in[15], *b2   =(const float*)d_in[16];
  const float* W3   =(const float*)d_in[17], *b3   =(const float*)d_in[18];
  const float* W_proj=(const float*)d_in[19],*b_proj=(const float*)d_in[20];

  float* out = (float*)d_out;
  float* out_deter = out;                          // [B,T,D]
  float* out_stoch = out + (size_t)B*T*D;          // [B,T,S,C]
  float* out_prior = out_stoch + (size_t)B*T*SC;   // [B,T,S,C]
  float* out_post  = out_prior + (size_t)B*T*SC;   // [B,T,S,C]

  k_rssm<<<NBLK, NTH>>>(embed, actions, isf,
                        W_in, b_in, W_blk, b_blk, W_ih, b_ih, W_hh, b_hh,
                        W1, b1, W2, b2, W3, b3, W_proj, b_proj,
                        out_deter, out_stoch, out_prior, out_post);
}

// round 15
// speedup vs baseline: 2.3870x; 1.2467x over previous
#include <cuda_runtime.h>
#include <cstdint>
#include <cstddef>

constexpr int B=256, T=64, H=512, S=32, C=32, A_=32, E=1024, BS=256;
constexpr int D=2048, X3H=1536, INX=1056, G3=768, NG=6144, DE_IN=3072, SC=1024;
constexpr int NBLK=296, NTH=256;

__device__ __align__(16) float g_deter[B*D];
__device__ __align__(16) float g_WinT [INX*X3H];  // W_in transposed [c][j]
__device__ __align__(16) float g_x   [B*X3H];     // x final (silu'd, biased)
__device__ int   g_sidx[B*S];                     // sampled idx (-1 = masked)
__device__ __align__(16) float g_hp  [4*B*D];     // h partials NEXT step (split4, masked)
__device__ __align__(16) float g_gip [3*B*NG];    // gi partials (split3, raw)
__device__ __align__(16) float g_gh  [B*NG];      // gh (biased)
__device__ __align__(16) float g_dein[B*DE_IN];
__device__ __align__(16) float g_h1  [6*2*B*H];   // M=512 (prior:4 slabs | post:6 slabs)
__device__ __align__(16) float g_h2  [4*2*B*H];   // split4 raw
__device__ __align__(16) float g_lp  [4*2*B*SC];  // logits partials (split4 raw)
__device__ __align__(16) float g_WprojT[DE_IN*D]; // W_proj^T  [k'][n]
__device__ __align__(16) float g_W1p [H*DE_IN];   // W1@W_proj [j][k']
__device__ __align__(16) float g_b1p [H];         // W1@b_proj + b1
__device__ unsigned g_cnt;
__device__ unsigned g_gen;
__device__ unsigned g_ctr[6*T + 1];

// ----------------------------- grid barrier --------------------------------
__device__ __forceinline__ void gridbar() {
  __syncthreads();
  if (threadIdx.x == 0) {
    unsigned gen = *(volatile unsigned*)&g_gen;
    __threadfence();
    if (atomicAdd(&g_cnt, 1u) == gridDim.x - 1u) {
      g_cnt = 0u;
      __threadfence();
      atomicExch(&g_gen, gen + 1u);
    } else {
      while (*(volatile unsigned*)&g_gen == gen) {}
    }
    __threadfence();
  }
  __syncthreads();
}

// ------------------------------ threefry2x32 -------------------------------
__device__ __forceinline__ void threefry(uint32_t k0, uint32_t k1, uint32_t x0,
                                         uint32_t x1, uint32_t& o0, uint32_t& o1) {
  uint32_t ks2 = 0x1BD11BDAu ^ k0 ^ k1;
#define TFR(x,r) x = (x<<r)|(x>>(32-r))
#define TF4(a,b,c,d) x0+=x1;TFR(x1,a);x1^=x0; x0+=x1;TFR(x1,b);x1^=x0; x0+=x1;TFR(x1,c);x1^=x0; x0+=x1;TFR(x1,d);x1^=x0;
  x0 += k0; x1 += k1;
  TF4(13,15,26,6);  x0 += k1;  x1 += ks2 + 1u;
  TF4(17,29,16,24); x0 += ks2; x1 += k0 + 2u;
  TF4(13,15,26,6);  x0 += k0;  x1 += k1 + 3u;
  TF4(17,29,16,24); x0 += k1;  x1 += ks2 + 4u;
  TF4(13,15,26,6);  x0 += ks2; x1 += k0 + 5u;
  o0 = x0; o1 = x1;
#undef TF4
#undef TFR
}

__device__ __forceinline__ float silu1(float v) { return v/(1.0f+expf(-v)); }

// ------------------------------ GEMM tile 128x64 ---------------------------
// Double-buffered smem pipeline; one __syncthreads per 16-k chunk.
// Aeff: NP=1 plain A0; NP>=2: (sum of NP partials)+Abias, optional SiLU.
// 256 threads, per-thread 8 rows x 4 cols. WMODE 0:+bias; 1:raw.
template <int NP,int SILU,int WMODE,int MASKED>
__device__ __forceinline__ void gemm(
    const float* __restrict__ A0, size_t pstr,
    const float* __restrict__ Abias, int lda,
    const float* __restrict__ W, int ldw, const float* __restrict__ bias,
    float* __restrict__ Cb, int ldc,
    int IN2, int kbase, int m0, int n0, int aColBase,
    const int* __restrict__ isf, int mt,
    float (*As)[16][136], float (*Ws)[16][68], float* mrow) {
  const int tid = threadIdx.x;
  if (MASKED) { if (tid < 128) mrow[tid] = isf[(size_t)(m0+tid)*T + mt] ? 0.0f : 1.0f; }
  __syncthreads();
  const int aoff = aColBase + kbase;
  const float* Ab0 = A0 + (size_t)m0*lda + aoff;
  const float* Wb  = W + (size_t)n0*ldw + kbase;
  const int alr = tid>>1, alq = (tid&1)<<3;
  const int wlr = tid>>2, wlq = (tid&3)<<2;
  const int ty = tid>>4, tx = tid&15;
  float acc[8][4] = {};
  float4 av0, av1, wv;

#define LOADCHUNK(KO) do {                                                   \
    size_t ao = (size_t)alr*lda + (KO) + alq;                                \
    av0 = *(const float4*)(Ab0 + ao);                                        \
    av1 = *(const float4*)(Ab0 + ao + 4);                                    \
    if (NP>=2) {                                                             \
      _Pragma("unroll")                                                      \
      for (int p = 1; p < NP; p++) {                                         \
        float4 b0v = *(const float4*)(Ab0 + p*pstr + ao);                    \
        float4 b1v = *(const float4*)(Ab0 + p*pstr + ao + 4);                \
        av0.x += b0v.x; av0.y += b0v.y; av0.z += b0v.z; av0.w += b0v.w;      \
        av1.x += b1v.x; av1.y += b1v.y; av1.z += b1v.z; av1.w += b1v.w;      \
      }                                                                      \
      float4 ab0 = *(const float4*)(Abias + aoff + (KO) + alq);              \
      float4 ab1 = *(const float4*)(Abias + aoff + (KO) + alq + 4);          \
      av0.x += ab0.x; av0.y += ab0.y; av0.z += ab0.z; av0.w += ab0.w;        \
      av1.x += ab1.x; av1.y += ab1.y; av1.z += ab1.z; av1.w += ab1.w;        \
      if (SILU) {                                                            \
        av0.x=silu1(av0.x); av0.y=silu1(av0.y);                              \
        av0.z=silu1(av0.z); av0.w=silu1(av0.w);                              \
        av1.x=silu1(av1.x); av1.y=silu1(av1.y);                              \
        av1.z=silu1(av1.z); av1.w=silu1(av1.w);                              \
      }                                                                      \
    }                                                                        \
    if (MASKED) {                                                            \
      float mm = mrow[alr];                                                  \
      av0.x*=mm; av0.y*=mm; av0.z*=mm; av0.w*=mm;                            \
      av1.x*=mm; av1.y*=mm; av1.z*=mm; av1.w*=mm;                            \
    }                                                                        \
    wv = *(const float4*)(Wb + (size_t)wlr*ldw + (KO) + wlq);                \
  } while(0)

#define STORECHUNK(BUF) do {                                                 \
    As[BUF][alq+0][alr]=av0.x; As[BUF][alq+1][alr]=av0.y;                    \
    As[BUF][alq+2][alr]=av0.z; As[BUF][alq+3][alr]=av0.w;                    \
    As[BUF][alq+4][alr]=av1.x; As[BUF][alq+5][alr]=av1.y;                    \
    As[BUF][alq+6][alr]=av1.z; As[BUF][alq+7][alr]=av1.w;                    \
    Ws[BUF][wlq+0][wlr]=wv.x; Ws[BUF][wlq+1][wlr]=wv.y;                      \
    Ws[BUF][wlq+2][wlr]=wv.z; Ws[BUF][wlq+3][wlr]=wv.w;                      \
  } while(0)

  LOADCHUNK(0);
  STORECHUNK(0);
  __syncthreads();
  int buf = 0;
  for (int k0 = 0; k0 < IN2; k0 += 16) {
    const bool more = (k0 + 16 < IN2);
    if (more) LOADCHUNK(k0 + 16);
#pragma unroll
    for (int kk = 0; kk < 16; kk++) {
      float4 a0 = *(const float4*)&As[buf][kk][ty<<3];
      float4 a1 = *(const float4*)&As[buf][kk][(ty<<3)+4];
      float4 w  = *(const float4*)&Ws[buf][kk][tx<<2];
      float am[8] = {a0.x,a0.y,a0.z,a0.w,a1.x,a1.y,a1.z,a1.w};
#pragma unroll
      for (int r = 0; r < 8; r++) {
        acc[r][0]+=am[r]*w.x; acc[r][1]+=am[r]*w.y;
        acc[r][2]+=am[r]*w.z; acc[r][3]+=am[r]*w.w;
      }
    }
    if (more) STORECHUNK(buf^1);
    __syncthreads();
    buf ^= 1;
  }
#undef LOADCHUNK
#undef STORECHUNK
#pragma unroll
  for (int r = 0; r < 8; r++) {
    int mi = m0 + (ty<<3) + r;
    int nb = n0 + (tx<<2);
    float4 v;
    v.x=acc[r][0]; v.y=acc[r][1]; v.z=acc[r][2]; v.w=acc[r][3];
    if (WMODE==0) {
      float4 bv = *(const float4*)(bias + nb);
      v.x+=bv.x; v.y+=bv.y; v.z+=bv.z; v.w+=bv.w;
    }
    *(float4*)(Cb + (size_t)mi*ldc + nb) = v;
  }
}

// ------------------------------ megakernel ---------------------------------
__global__ void __launch_bounds__(NTH, 2) k_rssm(
    const float* __restrict__ embed, const float* __restrict__ actions,
    const int* __restrict__ isf,
    const float* __restrict__ W_in,  const float* __restrict__ b_in,
    const float* __restrict__ W_blk, const float* __restrict__ b_blk,
    const float* __restrict__ W_ih,  const float* __restrict__ b_ih,
    const float* __restrict__ W_hh,  const float* __restrict__ b_hh,
    const float* __restrict__ W1,    const float* __restrict__ b1,
    const float* __restrict__ W2,    const float* __restrict__ b2,
    const float* __restrict__ W3,    const float* __restrict__ b3,
    const float* __restrict__ W_proj,const float* __restrict__ b_proj,
    float* __restrict__ out_deter, float* __restrict__ out_stoch,
    float* __restrict__ out_prior, float* __restrict__ out_post) {
  __shared__ __align__(16) float As[2][16][136];
  __shared__ __align__(16) float Ws[2][16][68];
  __shared__ float mrow[128];
  __shared__ int s_tl;
  const int bid = blockIdx.x;
  const int tid = threadIdx.x;
  const int gtid = bid*NTH + tid;
  const int gstep = gridDim.x*NTH;
  const int nwarp = gridDim.x*(NTH/32);
  const int wid = bid*(NTH/32) + (tid>>5);
  const int lane = tid & 31;
  const float TINYF = 1.17549435e-38f;
  const float UNIADD = (float)(0.01/32.0);
  const size_t PBD = (size_t)B*D;
  const size_t PBG = (size_t)B*NG;
  const size_t PBH = (size_t)2*B*H;
  const size_t PBL = (size_t)2*B*SC;

#define POP(pid) ({ if (tid==0) s_tl = (int)atomicAdd(&g_ctr[pid], 1u); \
                    __syncthreads(); int _v = s_tl; _v; })

  // ---- init ----
  for (int i = gtid; i < 6*T + 1; i += gstep) g_ctr[i] = 0u;
  for (int i = gtid; i < B*D; i += gstep) g_deter[i] = 0.0f;
  for (size_t i = gtid; i < 4*PBD; i += gstep) g_hp[i] = 0.0f;   // h for t=0
  for (int i = gtid; i < B*S; i += gstep) g_sidx[i] = -1;        // stoch0 = 0
  for (size_t i = gtid; i < (size_t)INX*X3H; i += gstep) {       // W_in transpose
    int c = (int)(i / X3H), j = (int)(i - (size_t)c*X3H);
    g_WinT[i] = W_in[(size_t)j*INX + c];
  }
  for (size_t i = gtid; i < (size_t)DE_IN*D; i += gstep) {       // W_proj transpose
    int kp = (int)(i / D), n = (int)(i - (size_t)kp*D);
    g_WprojT[i] = W_proj[(size_t)n*DE_IN + kp];
  }
  if (gtid < H) {                                                // b1p = W1@b_proj + b1
    float s = b1[gtid];
    const float* wr = W1 + (size_t)gtid*D;
    for (int d = 0; d < D; d++) s += wr[d]*b_proj[d];
    g_b1p[gtid] = s;
  }
  gridbar();
  // W1p = W1 @ W_proj  (192 tiles, K=2048, raw)
  for (;;) {
    int tl = POP(6*T); if (tl >= 192) break;
    gemm<1,0,1,0>(W1, 0, 0, D, g_WprojT, D, 0, g_W1p, DE_IN,
                  D, 0, (tl/48)<<7, (tl%48)<<6, 0, 0, 0, As, Ws, mrow);
  }
  gridbar();

  for (int t = 0; t < T; t++) {
    const int hlive = (t + 1 < T) ? 1 : 0;
    // P1a: x = silu(b_in + one-hot gather + W_in_act@action)
    for (int q = gtid; q < B*(X3H/4); q += gstep) {
      int b = q/(X3H/4), j = (q - b*(X3H/4))*4;
      float4 acc = *(const float4*)(b_in + j);
      const int* idxp = g_sidx + b*S;
#pragma unroll 4
      for (int s = 0; s < S; s++) {
        int c = idxp[s];
        if (c >= 0) {
          float4 wv = *(const float4*)(g_WinT + (size_t)(s*C + c)*X3H + j);
          acc.x+=wv.x; acc.y+=wv.y; acc.z+=wv.z; acc.w+=wv.w;
        }
      }
      const float* act = actions + ((size_t)b*T + t)*A_;
#pragma unroll 4
      for (int a = 0; a < A_; a++) {
        float fa = act[a];
        float4 wv = *(const float4*)(g_WinT + (size_t)(SC + a)*X3H + j);
        acc.x+=fa*wv.x; acc.y+=fa*wv.y; acc.z+=fa*wv.z; acc.w+=fa*wv.w;
      }
      acc.x=silu1(acc.x); acc.y=silu1(acc.y); acc.z=silu1(acc.z); acc.w=silu1(acc.w);
      *(float4*)(g_x + (size_t)b*X3H + j) = acc;
    }
    // P1b: gh = (sum4 hp + b_blk)@W_hh + b_hh  (192 tiles x 16ch, blockdiag)
    for (;;) {
      int tl = POP(t*6+0); if (tl >= 192) break;
      int n0 = (tl%96)<<6;
      gemm<4,0,0,0>(g_hp, PBD, b_blk, D, W_hh, BS, b_hh,
                    g_gh, NG, BS, 0,
                    (tl/96)<<7, n0, (n0/G3)*BS, 0, 0, As, Ws, mrow);
    }
    gridbar();
    // P2: gi partials = x@W_ih  (split3: 576 tiles x 32ch)
    for (;;) {
      int tl = POP(t*6+1); if (tl >= 576) break;
      int p = tl/192, i = tl%192;
      gemm<1,0,1,0>(g_x, 0, 0, X3H, W_ih, X3H, 0,
                    g_gip + p*PBG, NG, X3H/3, p*(X3H/3),
                    (i/96)<<7, (i%96)<<6, 0, 0, 0, As, Ws, mrow);
    }
    gridbar();
    // P3: GRU combine -> deter/out_deter/dein ; embed -> dein
    for (int i = gtid; i < B*D; i += gstep) {
      int b = i>>11, d = i & (D-1), k = d>>8, g = d & (BS-1);
      size_t base = (size_t)b*NG + k*G3 + g;
      float ir = (g_gip[base]      + g_gip[PBG+base])      + g_gip[2*PBG+base]      + b_ih[k*G3+g];
      float iz = (g_gip[base+BS]   + g_gip[PBG+base+BS])   + g_gip[2*PBG+base+BS]   + b_ih[k*G3+g+BS];
      float inn= (g_gip[base+2*BS] + g_gip[PBG+base+2*BS]) + g_gip[2*PBG+base+2*BS] + b_ih[k*G3+g+2*BS];
      float hr=g_gh[base], hz=g_gh[base+BS], hnn=g_gh[base+2*BS];
      float hv = ((g_hp[i] + g_hp[PBD+i]) + (g_hp[2*PBD+i] + g_hp[3*PBD+i])) + b_blk[d];
      float r = 1.0f/(1.0f+expf(-(ir+hr)));
      float z = 1.0f/(1.0f+expf(-(iz+hz)));
      float n = tanhf(inn + r*hnn);
      float dv = (1.0f - z)*n + z*hv;
      g_deter[i] = dv;
      g_dein[(size_t)b*DE_IN + d] = dv;
      out_deter[((size_t)b*T+t)*D + d] = dv;
    }
    for (int i = gtid; i < B*E; i += gstep) {
      int b = i>>10, j = i & (E-1);
      g_dein[(size_t)b*DE_IN + D + j] = embed[((size_t)b*T+t)*E + j];
    }
    gridbar();
    // P4': h1prior = deter@W1 (split4: 64 x 32ch)
    //      h1post  = dein@W1p (split6: 96 x 32ch)  [fused de+W1]
    //      hnext   = masked deter@W_blk (split4: 256 x 32ch)
    {
      int nP4 = 160 + hlive*256;
      for (;;) {
        int tl = POP(t*6+2); if (tl >= nP4) break;
        if (tl < 64) {
          int p = tl/16, i = tl%16;
          gemm<1,0,1,0>(g_deter, 0, 0, D, W1, D, 0, g_h1 + p*PBH, H,
                        D/4, p*(D/4), (i/8)<<7, (i%8)<<6, 0, 0, 0, As, Ws, mrow);
        } else if (tl < 160) {
          int j = tl-64, p = j/16, i = j%16;
          gemm<1,0,1,0>(g_dein - (size_t)256*DE_IN, 0, 0, DE_IN,
                        g_W1p, DE_IN, 0, g_h1 + p*PBH, H,
                        DE_IN/6, p*(DE_IN/6), 256 + ((i/8)<<7), (i%8)<<6,
                        0, 0, 0, As, Ws, mrow);
        } else {
          int j = tl-160, p = j/64, i = j%64;
          gemm<1,0,1,1>(g_deter, 0, 0, D, W_blk, D, 0,
                        g_hp + p*PBD, D, D/4, p*(D/4),
                        (i/32)<<7, (i&31)<<6, 0, isf, t+1, As, Ws, mrow);
        }
      }
    }
    gridbar();
    // P5': h2 partials = silu(h1-combine + bias)@W2, split4: 128 x 8ch
    //      prior rows: NP=4 + b1 ; post rows: NP=6 + b1p
    for (;;) {
      int tl = POP(t*6+3); if (tl >= 128) break;
      int p = tl/32, i = tl%32;
      int m0 = (i/8)<<7, n0 = (i%8)<<6;
      if (m0 < 256)
        gemm<4,1,1,0>(g_h1, PBH, b1, H, W2, H, 0,
                      g_h2 + p*PBH, H, H/4, p*(H/4), m0, n0, 0, 0, 0, As, Ws, mrow);
      else
        gemm<6,1,1,0>(g_h1, PBH, g_b1p, H, W2, H, 0,
                      g_h2 + p*PBH, H, H/4, p*(H/4), m0, n0, 0, 0, 0, As, Ws, mrow);
    }
    gridbar();
    // P6': logit partials = silu(h2-combine4 + b2)@W3, split4: 256 x 8ch
    for (;;) {
      int tl = POP(t*6+4); if (tl >= 256) break;
      int p = tl/64, i = tl%64;
      gemm<4,1,1,0>(g_h2, PBH, b2, H, W3, H, 0,
                    g_lp + p*PBL, SC, H/4, p*(H/4),
                    (i/16)<<7, (i%16)<<6, 0, 0, 0, As, Ws, mrow);
    }
    gridbar();
    // P8: prior combine -> out_prior ; sample(post combine) -> out_post/stoch/sidx
    for (int i = gtid; i < B*SC; i += gstep) {
      int b = i>>10, j = i & (SC-1);
      out_prior[((size_t)b*T+t)*SC + j] =
        ((g_lp[i] + g_lp[PBL+i]) + (g_lp[2*PBL+i] + g_lp[3*PBL+i])) + b3[j];
    }
    {
      uint32_t k0, k1;
      threefry(0u, 42u, 0u, (uint32_t)t, k0, k1);   // fold_in(key(42), t)
      for (int gw = wid; gw < 128*32; gw += nwarp) {
        int b0 = gw >> 5, s = gw & 31;
        uint32_t nA = (uint32_t)(b0*SC + s*C + lane);
        uint32_t a0,a1,c0,c1;
        threefry(k0,k1,0u,nA,a0,a1);
        threefry(k0,k1,0u,nA + (uint32_t)(128*SC),c0,c1);
        uint32_t bitsH[2] = { a0^a1, c0^c1 };
#pragma unroll
        for (int half = 0; half < 2; half++) {
          int b = b0 + half*128;
          size_t li = (size_t)(256+b)*SC + s*C + lane;
          float lg = ((g_lp[li] + g_lp[PBL+li]) + (g_lp[2*PBL+li] + g_lp[3*PBL+li]))
                     + b3[s*C + lane];
          out_post[((size_t)b*T+t)*SC + s*C + lane] = lg;
          float m = lg;
          for (int o = 16; o; o >>= 1) m = fmaxf(m, __shfl_xor_sync(~0u, m, o));
          float e = expf(lg - m), sum = e;
          for (int o = 16; o; o >>= 1) sum += __shfl_xor_sync(~0u, sum, o);
          float p = 0.99f*(e/sum) + UNIADD;
          float uf = __uint_as_float((bitsH[half]>>9) | 0x3f800000u) - 1.0f;
          uf = fmaxf(uf + TINYF, TINYF);
          float val = -logf(-logf(uf)) + logf(p);
          float bv = val; int bidx = lane;
          for (int o = 16; o; o >>= 1) {
            float ov = __shfl_xor_sync(~0u, bv, o);
            int   oi = __shfl_xor_sync(~0u, bidx, o);
            if (ov > bv || (ov == bv && oi < bidx)) { bv = ov; bidx = oi; }
          }
          float oneh = (lane == bidx) ? 1.0f : 0.0f;
          out_stoch[((size_t)b*T+t)*SC + s*C + lane] = oneh;
          if (lane == 0 && t + 1 < T)
            g_sidx[(size_t)b*S + s] = isf[(size_t)b*T + t + 1] ? -1 : bidx;
        }
      }
    }
    gridbar();
  }
#undef POP
}

extern "C" void kernel_launch(void* const* d_in, const int* in_sizes, int n_in,
                              void* d_out, int out_size) {
  const float* embed  =(const float*)d_in[0];
  const float* actions=(const float*)d_in[1];
  const int*   isf    =(const int*)  d_in[2];
  const float* W_in =(const float*)d_in[5],  *b_in =(const float*)d_in[6];
  const float* W_blk=(const float*)d_in[7],  *b_blk=(const float*)d_in[8];
  const float* W_ih =(const float*)d_in[9],  *b_ih =(const float*)d_in[10];
  const float* W_hh =(const float*)d_in[11], *b_hh =(const float*)d_in[12];
  const float* W1   =(const float*)d_in[13], *b1   =(const float*)d_in[14];
  const float* W2   =(const float*)d_in[15], *b2   =(const float*)d_in[16];
  const float* W3   =(const float*)d_in[17], *b3   =(const float*)d_in[18];
  const float* W_proj=(const float*)d_in[19],*b_proj=(const float*)d_in[20];

  float* out = (float*)d_out;
  float* out_deter = out;                          // [B,T,D]
  float* out_stoch = out + (size_t)B*T*D;          // [B,T,S,C]
  float* out_prior = out_stoch + (size_t)B*T*SC;   // [B,T,S,C]
  float* out_post  = out_prior + (size_t)B*T*SC;   // [B,T,S,C]

  k_rssm<<<NBLK, NTH>>>(embed, actions, isf,
                        W_in, b_in, W_blk, b_blk, W_ih, b_ih, W_hh, b_hh,
                        W1, b1, W2, b2, W3, b3, W_proj, b_proj,
                        out_deter, out_stoch, out_prior, out_post);
}